// round 8
// baseline (speedup 1.0000x reference)
#include <cuda_runtime.h>
#include <math.h>

#define Bb 8
#define Ss 4096
#define Dd 1024
#define Nn 16
#define Pp 4
#define NP 64
#define Hh 2048
#define BS 32768
#define OUT_CMB 134217728ll
#define OUT_LOSS 136314880ll

typedef unsigned long long u64;
__device__ __forceinline__ u64 d2(float v) {
    u64 r; asm("mov.b64 %0, {%1,%1};" : "=l"(r) : "f"(v)); return r;
}
__device__ __forceinline__ u64 f2fma(u64 a, u64 b, u64 c) {
    u64 d; asm("fma.rn.f32x2 %0, %1, %2, %3;" : "=l"(d) : "l"(a), "l"(b), "l"(c)); return d;
}
__device__ __forceinline__ float2 upk(u64 v) {
    float2 f; asm("mov.b64 {%0,%1}, %2;" : "=f"(f.x), "=f"(f.y) : "l"(v)); return f;
}

__device__ float g_phn[Dd * NP];
__device__ float g_rinv[BS];
__device__ float g_E[(size_t)BS * NP];
__device__ float g_sumS[Bb * NP];
__device__ float g_sumC[BS];
__device__ float g_esp[BS * Pp];
__device__ float g_Z[Bb];
__device__ float g_pt[Bb * Pp];
__device__ float g_xs[Bb * NP * Dd];
__device__ float g_h[Nn * 32 * Hh];
__device__ float g_r[Bb * NP * Dd];

__device__ __forceinline__ float red16(float v) {
    v += __shfl_xor_sync(0xffffffffu, v, 1);
    v += __shfl_xor_sync(0xffffffffu, v, 2);
    v += __shfl_xor_sync(0xffffffffu, v, 4);
    v += __shfl_xor_sync(0xffffffffu, v, 8);
    return v;
}

__global__ void k_init(float* __restrict__ out) {
    int t = threadIdx.x;
    if (t < Bb * NP) g_sumS[t] = 0.f;
    if (t < Bb) g_Z[t] = 0.f;
    if (t < Bb * Pp) g_pt[t] = 0.f;
    if (t == 0) out[OUT_LOSS] = 0.f;
}

__global__ void k_phinorm(const float* __restrict__ phi, const float* __restrict__ scale) {
    const int c = blockIdx.x;
    float s = 0.f;
    for (int d = threadIdx.x; d < Dd; d += 256) {
        float v = phi[d * NP + c];
        s += v * v;
    }
    __shared__ float red[256];
    red[threadIdx.x] = s;
    __syncthreads();
    for (int o = 128; o > 0; o >>= 1) {
        if (threadIdx.x < o) red[threadIdx.x] += red[threadIdx.x + o];
        __syncthreads();
    }
    const float inv = scale[0] / fmaxf(sqrtf(red[0]), 1e-12f);
    for (int d = threadIdx.x; d < Dd; d += 256)
        g_phn[d * NP + c] = phi[d * NP + c] * inv;
}

// logits GEMM [128 rows x 64 cols per block], 512 thr, fused row-norm + softmax stats
__global__ __launch_bounds__(512, 2) void k_logits(const float* __restrict__ x, float* __restrict__ out) {
    __shared__ float sA[32][132];
    __shared__ float sB[32][68];
    __shared__ float sred[32][64];
    __shared__ float srinv[128];
    const int m0 = blockIdx.x * 128;
    const int b = m0 >> 12;
    const int tid = threadIdx.x;
    const int ty = tid >> 4, tx = tid & 15;      // ty:0..31 (4 rows), tx:0..15 (4 cols)
    const int r0 = tid >> 3, kq = tid & 7;       // loader mapping: rows r0, r0+64
    u64 acc[2][4];
#pragma unroll
    for (int q = 0; q < 2; ++q)
#pragma unroll
        for (int j = 0; j < 4; ++j) acc[q][j] = 0ull;
    float sq0 = 0.f, sq1 = 0.f;

    for (int k0 = 0; k0 < Dd; k0 += 32) {
        {
            float4 v = *(const float4*)&x[(size_t)(m0 + r0) * Dd + k0 + kq * 4];
            sq0 = fmaf(v.x, v.x, sq0); sq0 = fmaf(v.y, v.y, sq0);
            sq0 = fmaf(v.z, v.z, sq0); sq0 = fmaf(v.w, v.w, sq0);
            sA[kq * 4 + 0][r0] = v.x; sA[kq * 4 + 1][r0] = v.y;
            sA[kq * 4 + 2][r0] = v.z; sA[kq * 4 + 3][r0] = v.w;
            float4 w = *(const float4*)&x[(size_t)(m0 + r0 + 64) * Dd + k0 + kq * 4];
            sq1 = fmaf(w.x, w.x, sq1); sq1 = fmaf(w.y, w.y, sq1);
            sq1 = fmaf(w.z, w.z, sq1); sq1 = fmaf(w.w, w.w, sq1);
            sA[kq * 4 + 0][r0 + 64] = w.x; sA[kq * 4 + 1][r0 + 64] = w.y;
            sA[kq * 4 + 2][r0 + 64] = w.z; sA[kq * 4 + 3][r0 + 64] = w.w;
        }
        {
            int k = tid >> 4, cq = tid & 15;
            *(float4*)&sB[k][cq * 4] = *(const float4*)&g_phn[(k0 + k) * NP + cq * 4];
        }
        __syncthreads();
#pragma unroll
        for (int k = 0; k < 32; ++k) {
            ulonglong2 ap = *(const ulonglong2*)&sA[k][ty * 4];
            float4 bv = *(const float4*)&sB[k][tx * 4];
            u64 bd[4] = {d2(bv.x), d2(bv.y), d2(bv.z), d2(bv.w)};
#pragma unroll
            for (int j = 0; j < 4; ++j) {
                acc[0][j] = f2fma(ap.x, bd[j], acc[0][j]);
                acc[1][j] = f2fma(ap.y, bd[j], acc[1][j]);
            }
        }
        __syncthreads();
    }

    // finish row norms (reduce over 8 loader lanes per row; lanes r0*8+kq consecutive)
    sq0 += __shfl_xor_sync(0xffffffffu, sq0, 1);
    sq0 += __shfl_xor_sync(0xffffffffu, sq0, 2);
    sq0 += __shfl_xor_sync(0xffffffffu, sq0, 4);
    sq1 += __shfl_xor_sync(0xffffffffu, sq1, 1);
    sq1 += __shfl_xor_sync(0xffffffffu, sq1, 2);
    sq1 += __shfl_xor_sync(0xffffffffu, sq1, 4);
    if (kq == 0) {
        float i0 = 1.f / fmaxf(sqrtf(sq0), 1e-12f);
        float i1 = 1.f / fmaxf(sqrtf(sq1), 1e-12f);
        srinv[r0] = i0; srinv[r0 + 64] = i1;
        g_rinv[m0 + r0] = i0; g_rinv[m0 + r0 + 64] = i1;
    }
    __syncthreads();

    float accf[4][4];
#pragma unroll
    for (int q = 0; q < 2; ++q)
#pragma unroll
        for (int j = 0; j < 4; ++j) {
            float2 f = upk(acc[q][j]);
            accf[2 * q][j] = f.x;
            accf[2 * q + 1][j] = f.y;
        }

    float cs0 = 0.f, cs1 = 0.f, cs2 = 0.f, cs3 = 0.f;
#pragma unroll
    for (int i = 0; i < 4; ++i) {
        const int m = m0 + ty * 4 + i;
        const float ri = srinv[ty * 4 + i];
        float e0 = __expf(accf[i][0] * ri);
        float e1 = __expf(accf[i][1] * ri);
        float e2 = __expf(accf[i][2] * ri);
        float e3 = __expf(accf[i][3] * ri);
        *(float4*)&g_E[(size_t)m * NP + tx * 4] = make_float4(e0, e1, e2, e3);
        cs0 += e0; cs1 += e1; cs2 += e2; cs3 += e3;
        float s0 = red16(e0), s1 = red16(e1), s2 = red16(e2), s3 = red16(e3);
        float sc = s0 + s1 + s2 + s3;
        float inv = 1.f / sc;
        *(float4*)&out[OUT_CMB + (size_t)m * NP + tx * 4] =
            make_float4(e0 * inv, e1 * inv, e2 * inv, e3 * inv);
        if (tx == 0) {
            *(float4*)&g_esp[m * 4] = make_float4(s0, s1, s2, s3);
            g_sumC[m] = sc;
        }
    }
    *(float4*)&sred[ty][tx * 4] = make_float4(cs0, cs1, cs2, cs3);
    __syncthreads();
    if (tid < 64) {
        float s = 0.f;
#pragma unroll
        for (int r = 0; r < 32; ++r) s += sred[r][tid];
        atomicAdd(&g_sumS[b * NP + tid], s);
    }
}

__global__ void k_bstats() {
    const int b = blockIdx.x;
    const int t = threadIdx.x;
    float z = 0.f, p0 = 0.f, p1 = 0.f, p2 = 0.f, p3 = 0.f;
    for (int s = t; s < Ss; s += 256) {
        int m = b * Ss + s;
        z += g_sumC[m];
        float4 e = *(const float4*)&g_esp[m * 4];
        p0 += e.x; p1 += e.y; p2 += e.z; p3 += e.w;
    }
    __shared__ float sm[5][256];
    sm[0][t] = z; sm[1][t] = p0; sm[2][t] = p1; sm[3][t] = p2; sm[4][t] = p3;
    __syncthreads();
    for (int o = 128; o > 0; o >>= 1) {
        if (t < o) {
#pragma unroll
            for (int q = 0; q < 5; ++q) sm[q][t] += sm[q][t + o];
        }
        __syncthreads();
    }
    if (t == 0) {
        g_Z[b] = sm[0][0];
        g_pt[b * 4 + 0] = sm[1][0];
        g_pt[b * 4 + 1] = sm[2][0];
        g_pt[b * 4 + 2] = sm[3][0];
        g_pt[b * 4 + 3] = sm[4][0];
    }
}

__global__ void k_mi(float* __restrict__ out) {
    const int idx = blockIdx.x * 256 + threadIdx.x;
    const int b = idx >> 12;
    const double invZ = 1.0 / (double)g_Z[b];
    float4 e = *(const float4*)&g_esp[idx * 4];
    const double pm = (double)g_sumC[idx] * invZ;
    float4 pt = *(const float4*)&g_pt[b * 4];
    double local = 0.0;
    { double pmt = (double)e.x * invZ; local += pmt * log(pmt / (pm * ((double)pt.x * invZ)) + 1e-10); }
    { double pmt = (double)e.y * invZ; local += pmt * log(pmt / (pm * ((double)pt.y * invZ)) + 1e-10); }
    { double pmt = (double)e.z * invZ; local += pmt * log(pmt / (pm * ((double)pt.z * invZ)) + 1e-10); }
    { double pmt = (double)e.w * invZ; local += pmt * log(pmt / (pm * ((double)pt.w * invZ)) + 1e-10); }
    __shared__ double red[256];
    red[threadIdx.x] = local;
    __syncthreads();
    for (int o = 128; o > 0; o >>= 1) {
        if (threadIdx.x < o) red[threadIdx.x] += red[threadIdx.x + o];
        __syncthreads();
    }
    if (threadIdx.x == 0) atomicAdd(&out[OUT_LOSS], (float)(-red[0]));
}

__global__ void k_xsinit(const float* __restrict__ te) {
    const int row = blockIdx.x;
    const int p = row & 3;
    const int t = threadIdx.x;
    *(float4*)&g_xs[(size_t)row * Dd + t * 4] = *(const float4*)&te[p * Dd + t * 4];
}

// dispatch: xs[b,c,d] += sum_m (E*rinv)[m,c] * x[m,d] / sumS ; 512 thr, split-K 8
__global__ __launch_bounds__(512, 2) void k_dispatch(const float* __restrict__ x) {
    __shared__ float sA[32][68];
    __shared__ float sB[32][132];
    const int d0 = blockIdx.x * 128, b = blockIdx.y, ks = blockIdx.z;
    const int mstart = b * Ss + ks * 512;
    const int tid = threadIdx.x;
    const int ty = tid >> 4, tx = tid & 15;      // ty:0..31 (2 c), tx:0..15 (8 d)
    u64 acc[2][4];
#pragma unroll
    for (int i = 0; i < 2; ++i)
#pragma unroll
        for (int j = 0; j < 4; ++j) acc[i][j] = 0ull;

    for (int k0 = 0; k0 < 512; k0 += 32) {
        const int mb = mstart + k0;
        {
            int k = tid >> 4, cq = tid & 15;
            float ri = g_rinv[mb + k];
            float4 v = *(const float4*)&g_E[(size_t)(mb + k) * NP + cq * 4];
            v.x *= ri; v.y *= ri; v.z *= ri; v.w *= ri;
            *(float4*)&sA[k][cq * 4] = v;
        }
#pragma unroll
        for (int i = 0; i < 2; ++i) {
            int fidx = tid + i * 512;
            int k = fidx >> 5, dq = fidx & 31;
            *(float4*)&sB[k][dq * 4] = *(const float4*)&x[(size_t)(mb + k) * Dd + d0 + dq * 4];
        }
        __syncthreads();
#pragma unroll
        for (int k = 0; k < 32; ++k) {
            float2 av = *(const float2*)&sA[k][ty * 2];
            ulonglong2 b01 = *(const ulonglong2*)&sB[k][tx * 8];
            ulonglong2 b23 = *(const ulonglong2*)&sB[k][tx * 8 + 4];
            u64 bp[4] = {b01.x, b01.y, b23.x, b23.y};
            u64 a0 = d2(av.x), a1 = d2(av.y);
#pragma unroll
            for (int j = 0; j < 4; ++j) {
                acc[0][j] = f2fma(a0, bp[j], acc[0][j]);
                acc[1][j] = f2fma(a1, bp[j], acc[1][j]);
            }
        }
        __syncthreads();
    }
#pragma unroll
    for (int i = 0; i < 2; ++i) {
        const int c = ty * 2 + i;
        const float inv = 1.f / g_sumS[b * NP + c];
        float* dst = &g_xs[((size_t)(b * NP + c)) * Dd + d0 + tx * 8];
#pragma unroll
        for (int j = 0; j < 4; ++j) {
            float2 f = upk(acc[i][j]);
            atomicAdd(&dst[2 * j], f.x * inv);
            atomicAdd(&dst[2 * j + 1], f.y * inv);
        }
    }
}

// h = silu(xs @ W1 + b1) per expert n, 512 thr
__global__ __launch_bounds__(512, 2) void k_mlp1(const float* __restrict__ W1, const float* __restrict__ b1) {
    __shared__ float sA[32][36];
    __shared__ float sB[32][132];
    const int h0 = blockIdx.x * 128;
    const int n = blockIdx.y;
    const int tid = threadIdx.x;
    const int ty = tid >> 5, tx = tid & 31;      // ty:0..15 (2 rows), tx:0..31 (4 h)
    const float* W = W1 + (size_t)n * Dd * Hh;
    u64 acc[2][2];
    acc[0][0] = acc[0][1] = acc[1][0] = acc[1][1] = 0ull;

    const int r_ld = tid >> 3, kq_ld = tid & 7;
    const size_t rowoff = ((size_t)(((r_ld >> 2) * Nn + n) * Pp + (r_ld & 3))) * Dd;
    for (int k0 = 0; k0 < Dd; k0 += 32) {
        if (tid < 256) {
            float4 v = *(const float4*)&g_xs[rowoff + k0 + kq_ld * 4];
            sA[kq_ld * 4 + 0][r_ld] = v.x;
            sA[kq_ld * 4 + 1][r_ld] = v.y;
            sA[kq_ld * 4 + 2][r_ld] = v.z;
            sA[kq_ld * 4 + 3][r_ld] = v.w;
        }
#pragma unroll
        for (int i = 0; i < 2; ++i) {
            int fidx = tid + i * 512;
            int k = fidx >> 5, hq = fidx & 31;
            *(float4*)&sB[k][hq * 4] = *(const float4*)&W[(size_t)(k0 + k) * Hh + h0 + hq * 4];
        }
        __syncthreads();
#pragma unroll
        for (int k = 0; k < 32; ++k) {
            float2 av = *(const float2*)&sA[k][ty * 2];
            ulonglong2 bp = *(const ulonglong2*)&sB[k][tx * 4];
            u64 a0 = d2(av.x), a1 = d2(av.y);
            acc[0][0] = f2fma(a0, bp.x, acc[0][0]);
            acc[0][1] = f2fma(a0, bp.y, acc[0][1]);
            acc[1][0] = f2fma(a1, bp.x, acc[1][0]);
            acc[1][1] = f2fma(a1, bp.y, acc[1][1]);
        }
        __syncthreads();
    }
#pragma unroll
    for (int i = 0; i < 2; ++i) {
        const int r = ty * 2 + i;
        float2 f01 = upk(acc[i][0]);
        float2 f23 = upk(acc[i][1]);
        float vv[4] = {f01.x, f01.y, f23.x, f23.y};
#pragma unroll
        for (int j = 0; j < 4; ++j) {
            const int h = h0 + tx * 4 + j;
            float v = vv[j] + b1[n * Hh + h];
            g_h[((size_t)n * 32 + r) * Hh + h] = v / (1.f + __expf(-v));
        }
    }
}

__global__ void k_rinit(const float* __restrict__ b2) {
    const int row = blockIdx.x;
    const int n = (row >> 2) & 15;
    const int t = threadIdx.x;
    float4 a = *(const float4*)&g_xs[(size_t)row * Dd + t * 4];
    float4 c = *(const float4*)&b2[n * Dd + t * 4];
    a.x += c.x; a.y += c.y; a.z += c.z; a.w += c.w;
    *(float4*)&g_r[(size_t)row * Dd + t * 4] = a;
}

// r += h @ W2 ; 512 thr, split-K 4
__global__ __launch_bounds__(512, 2) void k_mlp2(const float* __restrict__ W2) {
    __shared__ float sA[32][36];
    __shared__ float sB[32][132];
    const int d0 = blockIdx.x * 128;
    const int n = blockIdx.y;
    const int ks = blockIdx.z;
    const int tid = threadIdx.x;
    const int ty = tid >> 5, tx = tid & 31;
    const float* W = W2 + (size_t)n * Hh * Dd;
    u64 acc[2][2];
    acc[0][0] = acc[0][1] = acc[1][0] = acc[1][1] = 0ull;

    const int r_ld = tid >> 3, kq_ld = tid & 7;
    const float* hrow = &g_h[((size_t)n * 32 + r_ld) * Hh + ks * 512];
    for (int k0 = 0; k0 < 512; k0 += 32) {
        if (tid < 256) {
            float4 v = *(const float4*)&hrow[k0 + kq_ld * 4];
            sA[kq_ld * 4 + 0][r_ld] = v.x;
            sA[kq_ld * 4 + 1][r_ld] = v.y;
            sA[kq_ld * 4 + 2][r_ld] = v.z;
            sA[kq_ld * 4 + 3][r_ld] = v.w;
        }
        const int kg = ks * 512 + k0;
#pragma unroll
        for (int i = 0; i < 2; ++i) {
            int fidx = tid + i * 512;
            int k = fidx >> 5, dq = fidx & 31;
            *(float4*)&sB[k][dq * 4] = *(const float4*)&W[(size_t)(kg + k) * Dd + d0 + dq * 4];
        }
        __syncthreads();
#pragma unroll
        for (int k = 0; k < 32; ++k) {
            float2 av = *(const float2*)&sA[k][ty * 2];
            ulonglong2 bp = *(const ulonglong2*)&sB[k][tx * 4];
            u64 a0 = d2(av.x), a1 = d2(av.y);
            acc[0][0] = f2fma(a0, bp.x, acc[0][0]);
            acc[0][1] = f2fma(a0, bp.y, acc[0][1]);
            acc[1][0] = f2fma(a1, bp.x, acc[1][0]);
            acc[1][1] = f2fma(a1, bp.y, acc[1][1]);
        }
        __syncthreads();
    }
#pragma unroll
    for (int i = 0; i < 2; ++i) {
        const int r = ty * 2 + i;
        const size_t row = ((size_t)((r >> 2) * Nn + n) * Pp + (r & 3));
        float* dst = &g_r[row * Dd + d0 + tx * 4];
        float2 f01 = upk(acc[i][0]);
        float2 f23 = upk(acc[i][1]);
        atomicAdd(&dst[0], f01.x);
        atomicAdd(&dst[1], f01.y);
        atomicAdd(&dst[2], f23.x);
        atomicAdd(&dst[3], f23.y);
    }
}

__global__ __launch_bounds__(256) void k_ln(const float* __restrict__ lg, const float* __restrict__ lb) {
    const int row = blockIdx.x;
    const int n = (row >> 2) & 15;
    const int t = threadIdx.x;
    float4 v = *(const float4*)&g_r[(size_t)row * Dd + t * 4];
    float s = v.x + v.y + v.z + v.w;
    float q = v.x * v.x + v.y * v.y + v.z * v.z + v.w * v.w;
    __shared__ float sm[2][256];
    sm[0][t] = s; sm[1][t] = q;
    __syncthreads();
    for (int o = 128; o > 0; o >>= 1) {
        if (t < o) { sm[0][t] += sm[0][t + o]; sm[1][t] += sm[1][t + o]; }
        __syncthreads();
    }
    const float mu = sm[0][0] * (1.f / Dd);
    const float var = sm[1][0] * (1.f / Dd) - mu * mu;
    const float rstd = rsqrtf(var + 1e-5f);
    float4 g = *(const float4*)&lg[n * Dd + t * 4];
    float4 be = *(const float4*)&lb[n * Dd + t * 4];
    v.x = (v.x - mu) * rstd * g.x + be.x;
    v.y = (v.y - mu) * rstd * g.y + be.y;
    v.z = (v.z - mu) * rstd * g.z + be.z;
    v.w = (v.w - mu) * rstd * g.w + be.w;
    *(float4*)&g_r[(size_t)row * Dd + t * 4] = v;
}

__global__ __launch_bounds__(256) void k_combine(float* __restrict__ out) {
    const int m0 = blockIdx.x * 64;
    const int t = blockIdx.y;
    const int b = blockIdx.z;
    const int tid = threadIdx.x;
    ulonglong2 ysp[Nn];
#pragma unroll
    for (int n = 0; n < Nn; ++n)
        ysp[n] = *(const ulonglong2*)&g_r[((size_t)((b * Nn + n) * Pp + t)) * Dd + tid * 4];
    __shared__ float w[64][16];
#pragma unroll
    for (int i = 0; i < 4; ++i) {
        int idx = tid + i * 256;
        int tok = idx >> 4, nn = idx & 15;
        w[tok][nn] = out[OUT_CMB + (size_t)(b * Ss + m0 + tok) * NP + nn * 4 + t];
    }
    __syncthreads();
    float* dst = &out[(size_t)t * Bb * Ss * Dd + (size_t)(b * Ss + m0) * Dd + tid * 4];
#pragma unroll 4
    for (int tok = 0; tok < 64; ++tok) {
        u64 o0 = 0ull, o1 = 0ull;
#pragma unroll
        for (int n = 0; n < Nn; ++n) {
            u64 wd = d2(w[tok][n]);
            o0 = f2fma(wd, ysp[n].x, o0);
            o1 = f2fma(wd, ysp[n].y, o1);
        }
        ulonglong2 ov; ov.x = o0; ov.y = o1;
        *(ulonglong2*)&dst[(size_t)tok * Dd] = ov;
    }
}

extern "C" void kernel_launch(void* const* d_in, const int* in_sizes, int n_in,
                              void* d_out, int out_size) {
    const float* x = (const float*)d_in[0];
    const float* phi = (const float*)d_in[1];
    const float* scale = (const float*)d_in[2];
    const float* te = (const float*)d_in[3];
    const float* W1 = (const float*)d_in[4];
    const float* b1 = (const float*)d_in[5];
    const float* W2 = (const float*)d_in[6];
    const float* b2 = (const float*)d_in[7];
    const float* lg = (const float*)d_in[8];
    const float* lb = (const float*)d_in[9];
    float* out = (float*)d_out;

    k_init<<<1, 512>>>(out);
    k_phinorm<<<NP, 256>>>(phi, scale);
    k_logits<<<BS / 128, 512>>>(x, out);
    k_bstats<<<Bb, 256>>>();
    k_mi<<<BS / 256, 256>>>(out);
    k_xsinit<<<Bb * NP, 256>>>(te);
    k_dispatch<<<dim3(8, Bb, 8), 512>>>(x);
    k_mlp1<<<dim3(16, Nn), 512>>>(W1, b1);
    k_rinit<<<Bb * NP, 256>>>(b2);
    k_mlp2<<<dim3(8, Nn, 4), 512>>>(W2);
    k_ln<<<Bb * NP, 256>>>(lg, lb);
    k_combine<<<dim3(Ss / 64, Pp, Bb), 256>>>(out);
}

// round 9
// speedup vs baseline: 1.3287x; 1.3287x over previous
#include <cuda_runtime.h>
#include <math.h>

#define Bb 8
#define Ss 4096
#define Dd 1024
#define Nn 16
#define Pp 4
#define NP 64
#define Hh 2048
#define BS 32768
#define OUT_CMB 134217728ll
#define OUT_LOSS 136314880ll

typedef unsigned long long u64;
__device__ __forceinline__ u64 d2(float v) {
    u64 r; asm("mov.b64 %0, {%1,%1};" : "=l"(r) : "f"(v)); return r;
}
__device__ __forceinline__ u64 f2fma(u64 a, u64 b, u64 c) {
    u64 d; asm("fma.rn.f32x2 %0, %1, %2, %3;" : "=l"(d) : "l"(a), "l"(b), "l"(c)); return d;
}
__device__ __forceinline__ float2 upk(u64 v) {
    float2 f; asm("mov.b64 {%0,%1}, %2;" : "=f"(f.x), "=f"(f.y) : "l"(v)); return f;
}

__device__ float g_phn[Dd * NP];
__device__ float g_rinv[BS];
__device__ float g_E[(size_t)BS * NP];
__device__ float g_sumS[Bb * NP];
__device__ float g_sumC[BS];
__device__ float g_esp[BS * Pp];
__device__ float g_Z[Bb];
__device__ float g_pt[Bb * Pp];
__device__ float g_xs[Bb * NP * Dd];
__device__ float g_h[Nn * 32 * Hh];
__device__ float g_r[Bb * NP * Dd];

__device__ __forceinline__ float red16(float v) {
    v += __shfl_xor_sync(0xffffffffu, v, 1);
    v += __shfl_xor_sync(0xffffffffu, v, 2);
    v += __shfl_xor_sync(0xffffffffu, v, 4);
    v += __shfl_xor_sync(0xffffffffu, v, 8);
    return v;
}

__global__ void k_init(float* __restrict__ out) {
    int t = threadIdx.x;
    if (t < Bb * NP) g_sumS[t] = 0.f;
    if (t < Bb) g_Z[t] = 0.f;
    if (t < Bb * Pp) g_pt[t] = 0.f;
    if (t == 0) out[OUT_LOSS] = 0.f;
}

__global__ void k_phinorm(const float* __restrict__ phi, const float* __restrict__ scale) {
    const int c = blockIdx.x;
    float s = 0.f;
    for (int d = threadIdx.x; d < Dd; d += 256) {
        float v = phi[d * NP + c];
        s += v * v;
    }
    __shared__ float red[256];
    red[threadIdx.x] = s;
    __syncthreads();
    for (int o = 128; o > 0; o >>= 1) {
        if (threadIdx.x < o) red[threadIdx.x] += red[threadIdx.x + o];
        __syncthreads();
    }
    const float inv = scale[0] / fmaxf(sqrtf(red[0]), 1e-12f);
    for (int d = threadIdx.x; d < Dd; d += 256)
        g_phn[d * NP + c] = phi[d * NP + c] * inv;
}

// logits GEMM: 64 rows x 64 cols per block (512 blocks), 256 thr,
// fused row-norm + softmax stats, f32x2 packed math.
__global__ __launch_bounds__(256) void k_logits(const float* __restrict__ x, float* __restrict__ out) {
    __shared__ float sA[32][68];
    __shared__ float sB[32][68];
    __shared__ float sred[16][64];
    __shared__ float srinv[64];
    const int m0 = blockIdx.x * 64;
    const int b = m0 >> 12;
    const int tid = threadIdx.x;
    const int ty = tid >> 4, tx = tid & 15;   // ty: 4 rows each; tx: 4 cols each
    const int r0 = tid >> 3, kq = tid & 7;    // loader rows r0, r0+32
    u64 acc[2][4];
#pragma unroll
    for (int q = 0; q < 2; ++q)
#pragma unroll
        for (int j = 0; j < 4; ++j) acc[q][j] = 0ull;
    float sq0 = 0.f, sq1 = 0.f;

    for (int k0 = 0; k0 < Dd; k0 += 32) {
        {
            float4 v = *(const float4*)&x[(size_t)(m0 + r0) * Dd + k0 + kq * 4];
            sq0 = fmaf(v.x, v.x, sq0); sq0 = fmaf(v.y, v.y, sq0);
            sq0 = fmaf(v.z, v.z, sq0); sq0 = fmaf(v.w, v.w, sq0);
            sA[kq * 4 + 0][r0] = v.x; sA[kq * 4 + 1][r0] = v.y;
            sA[kq * 4 + 2][r0] = v.z; sA[kq * 4 + 3][r0] = v.w;
            float4 w = *(const float4*)&x[(size_t)(m0 + r0 + 32) * Dd + k0 + kq * 4];
            sq1 = fmaf(w.x, w.x, sq1); sq1 = fmaf(w.y, w.y, sq1);
            sq1 = fmaf(w.z, w.z, sq1); sq1 = fmaf(w.w, w.w, sq1);
            sA[kq * 4 + 0][r0 + 32] = w.x; sA[kq * 4 + 1][r0 + 32] = w.y;
            sA[kq * 4 + 2][r0 + 32] = w.z; sA[kq * 4 + 3][r0 + 32] = w.w;
        }
#pragma unroll
        for (int i = 0; i < 2; ++i) {
            int fidx = tid + i * 256;
            int k = fidx >> 4, cq = fidx & 15;
            *(float4*)&sB[k][cq * 4] = *(const float4*)&g_phn[(k0 + k) * NP + cq * 4];
        }
        __syncthreads();
#pragma unroll
        for (int k = 0; k < 32; ++k) {
            ulonglong2 ap = *(const ulonglong2*)&sA[k][ty * 4];
            float4 bv = *(const float4*)&sB[k][tx * 4];
            u64 bd[4] = {d2(bv.x), d2(bv.y), d2(bv.z), d2(bv.w)};
#pragma unroll
            for (int j = 0; j < 4; ++j) {
                acc[0][j] = f2fma(ap.x, bd[j], acc[0][j]);
                acc[1][j] = f2fma(ap.y, bd[j], acc[1][j]);
            }
        }
        __syncthreads();
    }

    // finish fused row norms: reduce over 8 loader lanes (kq) per row
    sq0 += __shfl_xor_sync(0xffffffffu, sq0, 1);
    sq0 += __shfl_xor_sync(0xffffffffu, sq0, 2);
    sq0 += __shfl_xor_sync(0xffffffffu, sq0, 4);
    sq1 += __shfl_xor_sync(0xffffffffu, sq1, 1);
    sq1 += __shfl_xor_sync(0xffffffffu, sq1, 2);
    sq1 += __shfl_xor_sync(0xffffffffu, sq1, 4);
    if (kq == 0) {
        float i0 = 1.f / fmaxf(sqrtf(sq0), 1e-12f);
        float i1 = 1.f / fmaxf(sqrtf(sq1), 1e-12f);
        srinv[r0] = i0; srinv[r0 + 32] = i1;
        g_rinv[m0 + r0] = i0; g_rinv[m0 + r0 + 32] = i1;
    }
    __syncthreads();

    float accf[4][4];
#pragma unroll
    for (int q = 0; q < 2; ++q)
#pragma unroll
        for (int j = 0; j < 4; ++j) {
            float2 f = upk(acc[q][j]);
            accf[2 * q][j] = f.x;
            accf[2 * q + 1][j] = f.y;
        }

    float cs0 = 0.f, cs1 = 0.f, cs2 = 0.f, cs3 = 0.f;
#pragma unroll
    for (int i = 0; i < 4; ++i) {
        const int m = m0 + ty * 4 + i;
        const float ri = srinv[ty * 4 + i];
        float e0 = __expf(accf[i][0] * ri);
        float e1 = __expf(accf[i][1] * ri);
        float e2 = __expf(accf[i][2] * ri);
        float e3 = __expf(accf[i][3] * ri);
        *(float4*)&g_E[(size_t)m * NP + tx * 4] = make_float4(e0, e1, e2, e3);
        cs0 += e0; cs1 += e1; cs2 += e2; cs3 += e3;
        float s0 = red16(e0), s1 = red16(e1), s2 = red16(e2), s3 = red16(e3);
        float sc = s0 + s1 + s2 + s3;
        float inv = 1.f / sc;
        *(float4*)&out[OUT_CMB + (size_t)m * NP + tx * 4] =
            make_float4(e0 * inv, e1 * inv, e2 * inv, e3 * inv);
        if (tx == 0) {
            *(float4*)&g_esp[m * 4] = make_float4(s0, s1, s2, s3);
            g_sumC[m] = sc;
        }
    }
    *(float4*)&sred[ty][tx * 4] = make_float4(cs0, cs1, cs2, cs3);
    __syncthreads();
    if (tid < 64) {
        float s = 0.f;
#pragma unroll
        for (int r = 0; r < 16; ++r) s += sred[r][tid];
        atomicAdd(&g_sumS[b * NP + tid], s);
    }
}

__global__ void k_bstats() {
    const int b = blockIdx.x;
    const int t = threadIdx.x;
    float z = 0.f, p0 = 0.f, p1 = 0.f, p2 = 0.f, p3 = 0.f;
    for (int s = t; s < Ss; s += 256) {
        int m = b * Ss + s;
        z += g_sumC[m];
        float4 e = *(const float4*)&g_esp[m * 4];
        p0 += e.x; p1 += e.y; p2 += e.z; p3 += e.w;
    }
    __shared__ float sm[5][256];
    sm[0][t] = z; sm[1][t] = p0; sm[2][t] = p1; sm[3][t] = p2; sm[4][t] = p3;
    __syncthreads();
    for (int o = 128; o > 0; o >>= 1) {
        if (t < o) {
#pragma unroll
            for (int q = 0; q < 5; ++q) sm[q][t] += sm[q][t + o];
        }
        __syncthreads();
    }
    if (t == 0) {
        g_Z[b] = sm[0][0];
        g_pt[b * 4 + 0] = sm[1][0];
        g_pt[b * 4 + 1] = sm[2][0];
        g_pt[b * 4 + 2] = sm[3][0];
        g_pt[b * 4 + 3] = sm[4][0];
    }
}

__global__ void k_mi(float* __restrict__ out) {
    const int idx = blockIdx.x * 256 + threadIdx.x;
    const int b = idx >> 12;
    const double invZ = 1.0 / (double)g_Z[b];
    float4 e = *(const float4*)&g_esp[idx * 4];
    const double pm = (double)g_sumC[idx] * invZ;
    float4 pt = *(const float4*)&g_pt[b * 4];
    double local = 0.0;
    { double pmt = (double)e.x * invZ; local += pmt * log(pmt / (pm * ((double)pt.x * invZ)) + 1e-10); }
    { double pmt = (double)e.y * invZ; local += pmt * log(pmt / (pm * ((double)pt.y * invZ)) + 1e-10); }
    { double pmt = (double)e.z * invZ; local += pmt * log(pmt / (pm * ((double)pt.z * invZ)) + 1e-10); }
    { double pmt = (double)e.w * invZ; local += pmt * log(pmt / (pm * ((double)pt.w * invZ)) + 1e-10); }
    __shared__ double red[256];
    red[threadIdx.x] = local;
    __syncthreads();
    for (int o = 128; o > 0; o >>= 1) {
        if (threadIdx.x < o) red[threadIdx.x] += red[threadIdx.x + o];
        __syncthreads();
    }
    if (threadIdx.x == 0) atomicAdd(&out[OUT_LOSS], (float)(-red[0]));
}

__global__ void k_xsinit(const float* __restrict__ te) {
    const int row = blockIdx.x;
    const int p = row & 3;
    const int t = threadIdx.x;
    *(float4*)&g_xs[(size_t)row * Dd + t * 4] = *(const float4*)&te[p * Dd + t * 4];
}

// dispatch: xs[b,c,d] += sum_m (E*rinv)[m,c] * x[m,d] / sumS ; split-K over m (f32x2)
__global__ __launch_bounds__(256) void k_dispatch(const float* __restrict__ x) {
    __shared__ float sA[32][68];
    __shared__ float sB[32][132];
    const int d0 = blockIdx.x * 128, b = blockIdx.y, ks = blockIdx.z;
    const int mstart = b * Ss + ks * 1024;
    const int tid = threadIdx.x;
    const int ty = tid >> 4, tx = tid & 15;
    u64 acc[4][4];
#pragma unroll
    for (int i = 0; i < 4; ++i)
#pragma unroll
        for (int j = 0; j < 4; ++j) acc[i][j] = 0ull;

    for (int k0 = 0; k0 < 1024; k0 += 32) {
        const int mb = mstart + k0;
#pragma unroll
        for (int i = 0; i < 2; ++i) {
            int fidx = tid + i * 256;
            int k = fidx >> 4, cq = fidx & 15;
            float ri = g_rinv[mb + k];
            float4 v = *(const float4*)&g_E[(size_t)(mb + k) * NP + cq * 4];
            v.x *= ri; v.y *= ri; v.z *= ri; v.w *= ri;
            *(float4*)&sA[k][cq * 4] = v;
        }
#pragma unroll
        for (int i = 0; i < 4; ++i) {
            int fidx = tid + i * 256;
            int k = fidx >> 5, dq = fidx & 31;
            *(float4*)&sB[k][dq * 4] = *(const float4*)&x[(size_t)(mb + k) * Dd + d0 + dq * 4];
        }
        __syncthreads();
#pragma unroll
        for (int k = 0; k < 32; ++k) {
            float4 av = *(const float4*)&sA[k][ty * 4];
            ulonglong2 b01 = *(const ulonglong2*)&sB[k][tx * 8];
            ulonglong2 b23 = *(const ulonglong2*)&sB[k][tx * 8 + 4];
            u64 bp[4] = {b01.x, b01.y, b23.x, b23.y};
            u64 ad[4] = {d2(av.x), d2(av.y), d2(av.z), d2(av.w)};
#pragma unroll
            for (int i = 0; i < 4; ++i)
#pragma unroll
                for (int j = 0; j < 4; ++j) acc[i][j] = f2fma(ad[i], bp[j], acc[i][j]);
        }
        __syncthreads();
    }
#pragma unroll
    for (int i = 0; i < 4; ++i) {
        const int c = ty * 4 + i;
        const float inv = 1.f / g_sumS[b * NP + c];
        float* dst = &g_xs[((size_t)(b * NP + c)) * Dd + d0 + tx * 8];
#pragma unroll
        for (int j = 0; j < 4; ++j) {
            float2 f = upk(acc[i][j]);
            atomicAdd(&dst[2 * j], f.x * inv);
            atomicAdd(&dst[2 * j + 1], f.y * inv);
        }
    }
}

// h = silu(xs @ W1 + b1) per expert n (f32x2)
__global__ __launch_bounds__(256) void k_mlp1(const float* __restrict__ W1, const float* __restrict__ b1) {
    __shared__ float sA[32][36];
    __shared__ float sB[32][132];
    const int h0 = blockIdx.x * 128;
    const int n = blockIdx.y;
    const int tid = threadIdx.x;
    const int ty = tid >> 5, tx = tid & 31;
    const float* W = W1 + (size_t)n * Dd * Hh;
    u64 acc[4][2];
#pragma unroll
    for (int i = 0; i < 4; ++i) { acc[i][0] = 0ull; acc[i][1] = 0ull; }

    const int r_ld = tid >> 3, kq_ld = tid & 7;
    const size_t rowoff = ((size_t)(((r_ld >> 2) * Nn + n) * Pp + (r_ld & 3))) * Dd;
    for (int k0 = 0; k0 < Dd; k0 += 32) {
        {
            float4 v = *(const float4*)&g_xs[rowoff + k0 + kq_ld * 4];
            sA[kq_ld * 4 + 0][r_ld] = v.x;
            sA[kq_ld * 4 + 1][r_ld] = v.y;
            sA[kq_ld * 4 + 2][r_ld] = v.z;
            sA[kq_ld * 4 + 3][r_ld] = v.w;
        }
#pragma unroll
        for (int i = 0; i < 4; ++i) {
            int fidx = tid + i * 256;
            int k = fidx >> 5, hq = fidx & 31;
            *(float4*)&sB[k][hq * 4] = *(const float4*)&W[(size_t)(k0 + k) * Hh + h0 + hq * 4];
        }
        __syncthreads();
#pragma unroll
        for (int k = 0; k < 32; ++k) {
            float4 av = *(const float4*)&sA[k][ty * 4];
            ulonglong2 bp = *(const ulonglong2*)&sB[k][tx * 4];
            u64 ad[4] = {d2(av.x), d2(av.y), d2(av.z), d2(av.w)};
#pragma unroll
            for (int i = 0; i < 4; ++i) {
                acc[i][0] = f2fma(ad[i], bp.x, acc[i][0]);
                acc[i][1] = f2fma(ad[i], bp.y, acc[i][1]);
            }
        }
        __syncthreads();
    }
#pragma unroll
    for (int i = 0; i < 4; ++i) {
        const int r = ty * 4 + i;
        float2 f01 = upk(acc[i][0]);
        float2 f23 = upk(acc[i][1]);
        float vv[4] = {f01.x, f01.y, f23.x, f23.y};
#pragma unroll
        for (int j = 0; j < 4; ++j) {
            const int h = h0 + tx * 4 + j;
            float v = vv[j] + b1[n * Hh + h];
            g_h[((size_t)n * 32 + r) * Hh + h] = v / (1.f + __expf(-v));
        }
    }
}

__global__ void k_rinit(const float* __restrict__ b2) {
    const int row = blockIdx.x;
    const int n = (row >> 2) & 15;
    const int t = threadIdx.x;
    float4 a = *(const float4*)&g_xs[(size_t)row * Dd + t * 4];
    float4 c = *(const float4*)&b2[n * Dd + t * 4];
    a.x += c.x; a.y += c.y; a.z += c.z; a.w += c.w;
    *(float4*)&g_r[(size_t)row * Dd + t * 4] = a;
}

// r += h @ W2 ; split-K over H (f32x2)
__global__ __launch_bounds__(256) void k_mlp2(const float* __restrict__ W2) {
    __shared__ float sA[32][36];
    __shared__ float sB[32][132];
    const int d0 = blockIdx.x * 128;
    const int n = blockIdx.y;
    const int ks = blockIdx.z;
    const int tid = threadIdx.x;
    const int ty = tid >> 5, tx = tid & 31;
    const float* W = W2 + (size_t)n * Hh * Dd;
    u64 acc[4][2];
#pragma unroll
    for (int i = 0; i < 4; ++i) { acc[i][0] = 0ull; acc[i][1] = 0ull; }

    const int r_ld = tid >> 3, kq_ld = tid & 7;
    const float* hrow = &g_h[((size_t)n * 32 + r_ld) * Hh + ks * 1024];
    for (int k0 = 0; k0 < 1024; k0 += 32) {
        {
            float4 v = *(const float4*)&hrow[k0 + kq_ld * 4];
            sA[kq_ld * 4 + 0][r_ld] = v.x;
            sA[kq_ld * 4 + 1][r_ld] = v.y;
            sA[kq_ld * 4 + 2][r_ld] = v.z;
            sA[kq_ld * 4 + 3][r_ld] = v.w;
        }
        const int kg = ks * 1024 + k0;
#pragma unroll
        for (int i = 0; i < 4; ++i) {
            int fidx = tid + i * 256;
            int k = fidx >> 5, dq = fidx & 31;
            *(float4*)&sB[k][dq * 4] = *(const float4*)&W[(size_t)(kg + k) * Dd + d0 + dq * 4];
        }
        __syncthreads();
#pragma unroll
        for (int k = 0; k < 32; ++k) {
            float4 av = *(const float4*)&sA[k][ty * 4];
            ulonglong2 bp = *(const ulonglong2*)&sB[k][tx * 4];
            u64 ad[4] = {d2(av.x), d2(av.y), d2(av.z), d2(av.w)};
#pragma unroll
            for (int i = 0; i < 4; ++i) {
                acc[i][0] = f2fma(ad[i], bp.x, acc[i][0]);
                acc[i][1] = f2fma(ad[i], bp.y, acc[i][1]);
            }
        }
        __syncthreads();
    }
#pragma unroll
    for (int i = 0; i < 4; ++i) {
        const int r = ty * 4 + i;
        const size_t row = ((size_t)((r >> 2) * Nn + n) * Pp + (r & 3));
        float* dst = &g_r[row * Dd + d0 + tx * 4];
        float2 f01 = upk(acc[i][0]);
        float2 f23 = upk(acc[i][1]);
        atomicAdd(&dst[0], f01.x);
        atomicAdd(&dst[1], f01.y);
        atomicAdd(&dst[2], f23.x);
        atomicAdd(&dst[3], f23.y);
    }
}

__global__ __launch_bounds__(256) void k_ln(const float* __restrict__ lg, const float* __restrict__ lb) {
    const int row = blockIdx.x;
    const int n = (row >> 2) & 15;
    const int t = threadIdx.x;
    float4 v = *(const float4*)&g_r[(size_t)row * Dd + t * 4];
    float s = v.x + v.y + v.z + v.w;
    float q = v.x * v.x + v.y * v.y + v.z * v.z + v.w * v.w;
    __shared__ float sm[2][256];
    sm[0][t] = s; sm[1][t] = q;
    __syncthreads();
    for (int o = 128; o > 0; o >>= 1) {
        if (t < o) { sm[0][t] += sm[0][t + o]; sm[1][t] += sm[1][t + o]; }
        __syncthreads();
    }
    const float mu = sm[0][0] * (1.f / Dd);
    const float var = sm[1][0] * (1.f / Dd) - mu * mu;
    const float rstd = rsqrtf(var + 1e-5f);
    float4 g = *(const float4*)&lg[n * Dd + t * 4];
    float4 be = *(const float4*)&lb[n * Dd + t * 4];
    v.x = (v.x - mu) * rstd * g.x + be.x;
    v.y = (v.y - mu) * rstd * g.y + be.y;
    v.z = (v.z - mu) * rstd * g.z + be.z;
    v.w = (v.w - mu) * rstd * g.w + be.w;
    *(float4*)&g_r[(size_t)row * Dd + t * 4] = v;
}

__global__ __launch_bounds__(256) void k_combine(float* __restrict__ out) {
    const int m0 = blockIdx.x * 64;
    const int t = blockIdx.y;
    const int b = blockIdx.z;
    const int tid = threadIdx.x;
    ulonglong2 ysp[Nn];
#pragma unroll
    for (int n = 0; n < Nn; ++n)
        ysp[n] = *(const ulonglong2*)&g_r[((size_t)((b * Nn + n) * Pp + t)) * Dd + tid * 4];
    __shared__ float w[64][16];
#pragma unroll
    for (int i = 0; i < 4; ++i) {
        int idx = tid + i * 256;
        int tok = idx >> 4, nn = idx & 15;
        w[tok][nn] = out[OUT_CMB + (size_t)(b * Ss + m0 + tok) * NP + nn * 4 + t];
    }
    __syncthreads();
    float* dst = &out[(size_t)t * Bb * Ss * Dd + (size_t)(b * Ss + m0) * Dd + tid * 4];
#pragma unroll 4
    for (int tok = 0; tok < 64; ++tok) {
        u64 o0 = 0ull, o1 = 0ull;
#pragma unroll
        for (int n = 0; n < Nn; ++n) {
            u64 wd = d2(w[tok][n]);
            o0 = f2fma(wd, ysp[n].x, o0);
            o1 = f2fma(wd, ysp[n].y, o1);
        }
        ulonglong2 ov; ov.x = o0; ov.y = o1;
        *(ulonglong2*)&dst[(size_t)tok * Dd] = ov;
    }
}

extern "C" void kernel_launch(void* const* d_in, const int* in_sizes, int n_in,
                              void* d_out, int out_size) {
    const float* x = (const float*)d_in[0];
    const float* phi = (const float*)d_in[1];
    const float* scale = (const float*)d_in[2];
    const float* te = (const float*)d_in[3];
    const float* W1 = (const float*)d_in[4];
    const float* b1 = (const float*)d_in[5];
    const float* W2 = (const float*)d_in[6];
    const float* b2 = (const float*)d_in[7];
    const float* lg = (const float*)d_in[8];
    const float* lb = (const float*)d_in[9];
    float* out = (float*)d_out;

    k_init<<<1, 512>>>(out);
    k_phinorm<<<NP, 256>>>(phi, scale);
    k_logits<<<BS / 64, 256>>>(x, out);
    k_bstats<<<Bb, 256>>>();
    k_mi<<<BS / 256, 256>>>(out);
    k_xsinit<<<Bb * NP, 256>>>(te);
    k_dispatch<<<dim3(8, Bb, 4), 256>>>(x);
    k_mlp1<<<dim3(16, Nn), 256>>>(W1, b1);
    k_rinit<<<Bb * NP, 256>>>(b2);
    k_mlp2<<<dim3(8, Nn, 2), 256>>>(W2);
    k_ln<<<Bb * NP, 256>>>(lg, lb);
    k_combine<<<dim3(Ss / 64, Pp, Bb), 256>>>(out);
}